// round 12
// baseline (speedup 1.0000x reference)
#include <cuda_runtime.h>
#include <cub/block/block_radix_sort.cuh>
#include <math.h>
#include <float.h>
#include <limits.h>
#include <stdint.h>

#define SB 128
#define SV 128000
#define SQ (SV / 4)            // 32000 float4 per row
#define B2CAP 4096             // crossing-bucket gather capacity
#define HDCAP 4096             // head gather capacity (top_ks <= 2047)
#define HEADN 2048
#define SKIPBITS 0x2B800000u   // e < 2^-40: skip histogram (dS <= 1.2e-7 rel)
#define MASK42 ((1ull << 42) - 1ull)
#define K2T 256
typedef unsigned long long ull;

// ---------------------------------------------------------------------------
// Static device scratch
// ---------------------------------------------------------------------------
__device__ float    g_work[(size_t)SB * SV];        // e = exp(x - M), 65.5 MB
__device__ ull      g_histpart[(size_t)SB * 8 * 1024];  // per-block hist partials
__device__ ull      g_head[(size_t)SB * HDCAP];
__device__ ull      g_b2buf[(size_t)SB * B2CAP];
__device__ float    g_maxpart[SB * 8];
__device__ int      g_hcnt[SB];
__device__ int      g_bcnt[SB];
__device__ float    g_invf[SB];              // f32(1/S) == ps[0]
__device__ double   g_cm2[SB];               // p-mass strictly above crossing bucket
__device__ float    g_S2f[SB];               // nucleus mass (f32)
__device__ ull      g_kstar[SB];             // largest member key
__device__ ull      g_sampkey[SB];           // sampled element's key

// key48: ascending == p descending, index ascending (stable argsort ties)
__device__ __forceinline__ ull make_key(unsigned pb, int idx) {
    return (((ull)(0x7FFFFFFFu - pb)) << 17) | (unsigned)idx;
}
__device__ __forceinline__ float key_p(ull k) {
    return __uint_as_float(0x7FFFFFFFu - (unsigned)(k >> 17));
}
__device__ __forceinline__ int key_idx(ull k) { return (int)(k & 0x1FFFFull); }

// M = f32(Lmax/T): division by T>0 is monotone, so max of f32(l/T) = f32(max l / T)
__device__ __forceinline__ float row_M(int b, float T) {
    float m = g_maxpart[b * 8];
#pragma unroll
    for (int j = 1; j < 8; j++) m = fmaxf(m, g_maxpart[b * 8 + j]);
    return m / T;
}

// warp-aggregated filtered append (all lanes must call)
__device__ __forceinline__ void wagg_append(bool pred, ull key, int* cnt,
                                            ull* buf, int cap) {
    unsigned m = __ballot_sync(0xFFFFFFFFu, pred);
    if (m == 0) return;
    const int lane = threadIdx.x & 31;
    const int leader = __ffs(m) - 1;
    int pos0 = 0;
    if (lane == leader) pos0 = atomicAdd(cnt, __popc(m));
    pos0 = __shfl_sync(0xFFFFFFFFu, pos0, leader);
    if (pred) {
        int pos = pos0 + __popc(m & ((1u << lane) - 1u));
        if (pos < cap) buf[pos] = key;
    }
}

// ---------------------------------------------------------------------------
// K_max: per-row max of RAW logits + zero counters.  grid (8, SB) x 512.
// ---------------------------------------------------------------------------
__global__ __launch_bounds__(512) void k_max(const float* __restrict__ logits) {
    __shared__ float sf[512];
    const int b = blockIdx.y;
    const int bx = blockIdx.x;
    if (bx == 0 && threadIdx.x == 0) { g_hcnt[b] = 0; g_bcnt[b] = 0; }

    const float4* row = (const float4*)(logits + (size_t)b * SV);
    float m = -FLT_MAX;
#pragma unroll
    for (int j = 0; j < 8; j++) {
        int q = j * 4096 + bx * 512 + threadIdx.x;
        if (q < SQ) {
            float4 v = row[q];
            m = fmaxf(m, fmaxf(fmaxf(v.x, v.y), fmaxf(v.z, v.w)));
        }
    }
    sf[threadIdx.x] = m;
    __syncthreads();
    for (int o = 256; o > 0; o >>= 1) {
        if (threadIdx.x < o) sf[threadIdx.x] = fmaxf(sf[threadIdx.x], sf[threadIdx.x + o]);
        __syncthreads();
    }
    if (threadIdx.x == 0) g_maxpart[b * 8 + bx] = sf[0];
}

// ---------------------------------------------------------------------------
// K_exp: e = expf(l/T - M) -> g_work; exact packed smem histogram
// (count<<42 | sig24) with WARP-AGGREGATED atomics:
// match_any groups lanes hitting the same bucket; reduce_add sums their sigs
// (<= 32 * 2^24 < 2^32); one leader atomic per group.  Bit-identical result
// (integer adds commute).  grid (8, SB) x 512.
// ---------------------------------------------------------------------------
__device__ __forceinline__ void hist_add_agg(ull* hist, unsigned eb) {
    const bool v = (eb >= SKIPBITS);
    const unsigned bkt = v ? (eb >> 20) : 0xFFFFFFFFu;
    const unsigned grp = __match_any_sync(0xFFFFFFFFu, bkt);
    const unsigned sig = v ? ((eb & 0x7FFFFFu) | 0x800000u) : 0u;
    const unsigned ss = __reduce_add_sync(grp, sig);
    if (v && ((threadIdx.x & 31) == (unsigned)(__ffs(grp) - 1)))
        atomicAdd(&hist[bkt], ((ull)__popc(grp) << 42) | (ull)ss);
}

__global__ __launch_bounds__(512) void k_exp(const float* __restrict__ logits,
                                             const float* __restrict__ temps) {
    __shared__ ull hist[1024];
    hist[threadIdx.x] = 0ull;
    hist[threadIdx.x + 512] = 0ull;
    const int b = blockIdx.y;
    const float T = temps[b];
    const float M = row_M(b, T);
    const float4* row = (const float4*)(logits + (size_t)b * SV);
    float4* erow = (float4*)(g_work + (size_t)b * SV);
    __syncthreads();
#pragma unroll
    for (int j = 0; j < 8; j++) {
        int q = j * 4096 + blockIdx.x * 512 + threadIdx.x;
        const bool valid = (q < SQ);
        float4 l = valid ? row[q] : make_float4(-FLT_MAX, -FLT_MAX, -FLT_MAX, -FLT_MAX);
        float4 e;
        e.x = expf(l.x / T - M);
        e.y = expf(l.y / T - M);
        e.z = expf(l.z / T - M);
        e.w = expf(l.w / T - M);
        if (valid) erow[q] = e;
        hist_add_agg(hist, valid ? __float_as_uint(e.x) : 0u);
        hist_add_agg(hist, valid ? __float_as_uint(e.y) : 0u);
        hist_add_agg(hist, valid ? __float_as_uint(e.z) : 0u);
        hist_add_agg(hist, valid ? __float_as_uint(e.w) : 0u);
    }
    __syncthreads();
    ull* outp = &g_histpart[((size_t)(b * 8 + blockIdx.x)) << 10];
    outp[threadIdx.x] = hist[threadIdx.x];
    outp[threadIdx.x + 512] = hist[threadIdx.x + 512];
}

// ---------------------------------------------------------------------------
// K_gather: merge 8 hist partials; suffix scans -> S, invf, Bk, B2, cm2;
// then gather head + crossing-bucket keys reading precomputed e (g_work).
// grid (8, SB) x 512.
// ---------------------------------------------------------------------------
__global__ __launch_bounds__(512) void k_gather(const float* __restrict__ topps2) {
    __shared__ int    sh_i[1024];
    __shared__ double sh_d[1024];
    __shared__ int    s_B2, s_minb, s_Bk;
    __shared__ double s_cm2;

    const int b = blockIdx.y;
    const int bx = blockIdx.x;
    const int t = threadIdx.x;

    if (t == 0) { s_B2 = -1; s_minb = 1024; s_Bk = 0; }

    // ---- merge partials (identical in every block; 64KB L2 read) ----
    ull h0 = 0ull, h1 = 0ull;
#pragma unroll
    for (int j = 0; j < 8; j++) {
        const ull* p = &g_histpart[((size_t)(b * 8 + j)) << 10];
        h0 += p[t];
        h1 += p[512 + t];
    }
    const int c0 = (int)(h0 >> 42), c1i = (int)(h1 >> 42);
    sh_i[t] = c0;
    sh_i[512 + t] = c1i;
    sh_d[t] = ldexp((double)(h0 & MASK42), (t >> 3) - 150);
    sh_d[512 + t] = ldexp((double)(h1 & MASK42), ((512 + t) >> 3) - 150);
    __syncthreads();
    // suffix inclusive scans (toward higher bucket == higher p)
    for (int o = 1; o < 1024; o <<= 1) {
        int iv0 = 0, iv1 = 0; double dv0 = 0.0, dv1 = 0.0;
        if (t + o < 1024) { iv0 = sh_i[t + o]; dv0 = sh_d[t + o]; }
        if (512 + t + o < 1024) { iv1 = sh_i[512 + t + o]; dv1 = sh_d[512 + t + o]; }
        __syncthreads();
        sh_i[t] += iv0; sh_d[t] += dv0;
        sh_i[512 + t] += iv1; sh_d[512 + t] += dv1;
        __syncthreads();
    }
    const double S = sh_d[0];
    const double p2S = (double)topps2[b] * S;
    const float invf = (float)(1.0 / S);

    // selection at both owned positions
    {
        const int poss[2] = {t, 512 + t};
        const int cnts[2] = {c0, c1i};
#pragma unroll
        for (int z = 0; z < 2; z++) {
            const int pos = poss[z], cnt = cnts[z];
            const int    ccincl = sh_i[pos];
            const int    ccnext = (pos < 1023) ? sh_i[pos + 1] : 0;
            const double cmincl = sh_d[pos];
            const double cmnext = (pos < 1023) ? sh_d[pos + 1] : 0.0;
            if (ccincl >= HEADN && ccnext < HEADN) s_Bk = pos;
            if (cnt > 0) {
                atomicMin(&s_minb, pos);
                if (cmnext <= p2S && cmincl > p2S) { s_B2 = pos; s_cm2 = cmnext; }
            }
        }
    }
    __syncthreads();
    if (s_B2 < 0) {
        if (t == s_minb) { s_B2 = t; s_cm2 = (t < 1023) ? sh_d[t + 1] : 0.0; }
        else if (512 + t == s_minb) { s_B2 = 512 + t; s_cm2 = (512 + t < 1023) ? sh_d[513 + t] : 0.0; }
    }
    __syncthreads();
    const int B2 = s_B2, Bk = s_Bk;
    if (bx == 0 && t == 0) {
        g_invf[b] = invf;
        g_cm2[b] = s_cm2 / S;     // p-units mass strictly above crossing bucket
    }

    // ---- gather both lists from precomputed e ----
    const unsigned thk  = ((unsigned)Bk) << 20;
    const unsigned b2lo = ((unsigned)B2) << 20;
    const unsigned b2hi = b2lo + (1u << 20);
    const float4* row4 = (const float4*)(g_work + (size_t)b * SV);
    ull* hb = &g_head[(size_t)b * HDCAP];
    ull* bb = &g_b2buf[(size_t)b * B2CAP];
#pragma unroll
    for (int j = 0; j < 8; j++) {
        int q = j * 4096 + bx * 512 + t;
        bool valid = (q < SQ);
        float4 e = valid ? row4[q] : make_float4(0.f, 0.f, 0.f, 0.f);
        float ev[4] = {e.x, e.y, e.z, e.w};
#pragma unroll
        for (int c = 0; c < 4; c++) {
            unsigned eb = __float_as_uint(ev[c]);
            bool hh = valid && (eb >= thk);
            bool b2p = valid && (eb >= b2lo) && (eb < b2hi);
            // fast skip when the whole warp has no candidates (common case)
            if (__ballot_sync(0xFFFFFFFFu, hh || b2p)) {
                ull key = 0ull;
                if (hh || b2p) key = make_key(__float_as_uint(ev[c] * invf), q * 4 + c);
                wagg_append(hh, key, &g_hcnt[b], hb, HDCAP);
                wagg_append(b2p, key, &g_bcnt[b], bb, B2CAP);
            }
        }
    }
}

// ---------------------------------------------------------------------------
// K2: 256 blocks x 256 threads (2+ blocks/SM -> one latency wave).
//   role 0: crossing-bucket sort + f32 boundary walk -> Kstar, S2
//   role 1: head sort + filters + inverse-CDF sample -> token, sampkey
// Size-adaptive sorters (8/10/16 items) + runtime key rebasing.
// ---------------------------------------------------------------------------
typedef cub::BlockRadixSort<ull, K2T, 8>  SorterA;   // 2048
typedef cub::BlockRadixSort<ull, K2T, 10> SorterB;   // 2560
typedef cub::BlockRadixSort<ull, K2T, 16> SorterC;   // 4096 fallback
union SortTemp {
    SorterA::TempStorage a;
    SorterB::TempStorage b;
    SorterC::TempStorage c;
};

__device__ __forceinline__ ull blk_min(ull v, ull* sh) {
    const int t = threadIdx.x;
    sh[t] = v; __syncthreads();
    for (int o = K2T / 2; o > 0; o >>= 1) {
        if (t < o) sh[t] = min(sh[t], sh[t + o]);
        __syncthreads();
    }
    ull r = sh[0]; __syncthreads();
    return r;
}
__device__ __forceinline__ ull blk_max(ull v, ull* sh) {
    const int t = threadIdx.x;
    sh[t] = v; __syncthreads();
    for (int o = K2T / 2; o > 0; o >>= 1) {
        if (t < o) sh[t] = max(sh[t], sh[t + o]);
        __syncthreads();
    }
    ull r = sh[0]; __syncthreads();
    return r;
}

template <int IT>
__device__ __forceinline__ void load_striped(ull (&keys)[IT], const ull* buf, int n) {
    const int t = threadIdx.x;
#pragma unroll
    for (int i = 0; i < IT; i++) {
        int r = i * K2T + t;
        keys[i] = (r < n) ? buf[r] : ~0ull;
    }
}

// rebase -> sort -> unrebase.  Input striped, output blocked (sorted).
template <int IT, class TS>
__device__ void sort_rebased(ull (&keys)[IT], int n, TS& ts, ull* sh_u) {
    const int t = threadIdx.x;
    ull vmin = ~0ull, vmax = 0ull;
#pragma unroll
    for (int i = 0; i < IT; i++) {
        int r = i * K2T + t;
        if (r < n) { vmin = min(vmin, keys[i]); vmax = max(vmax, keys[i]); }
    }
    const ull kmin = blk_min(vmin, sh_u);
    const ull kmax = blk_max(vmax, sh_u);
    const ull kbase = kmin & ~0x1FFFFull;
    const int endbit = 64 - __clzll((long long)((kmax - kbase) | 1ull));
#pragma unroll
    for (int i = 0; i < IT; i++) {
        int r = i * K2T + t;
        if (r < n) keys[i] -= kbase;
    }
    cub::BlockRadixSort<ull, K2T, IT>(ts).Sort(keys, 0, endbit);
    __syncthreads();
#pragma unroll
    for (int i = 0; i < IT; i++) {
        int r = t * IT + i;
        if (r < n) keys[i] += kbase;
    }
}

// role-0 post-sort: double prefix + f32 boundary walk; writes Kstar, S2.
template <int IT>
__device__ void role0_post(ull (&keys)[IT], int bcnt, double cm2, float p2f,
                           int b, double* sh_d, int* sh_i) {
    __shared__ double sS2;
    __shared__ ull    sK;
    const int t = threadIdx.x;

    double loc = 0.0;
#pragma unroll
    for (int i = 0; i < IT; i++) {
        int r = t * IT + i;
        if (r < bcnt) loc += (double)key_p(keys[i]);
    }
    sh_d[t] = loc;
    __syncthreads();
    for (int o = 1; o < K2T; o <<= 1) {
        double v = (t >= o) ? sh_d[t - o] : 0.0;
        __syncthreads();
        sh_d[t] += v;
        __syncthreads();
    }
    const double base = (t > 0) ? sh_d[t - 1] : 0.0;

    int ff = INT_MAX;
    {
        double cum = cm2 + base;
#pragma unroll
        for (int i = 0; i < IT; i++) {
            int r = t * IT + i;
            if (r < bcnt) {
                float p = key_p(keys[i]);
                cum += (double)p;
                float cse = (float)cum;
                if (cse - p > p2f && r < ff) ff = r;
            }
        }
    }
    sh_i[t] = ff;
    __syncthreads();
    for (int o = K2T / 2; o > 0; o >>= 1) {
        if (t < o) sh_i[t] = min(sh_i[t], sh_i[t + o]);
        __syncthreads();
    }
    const int r2in = min(sh_i[0], bcnt);

    if (t == 0) {
        sS2 = cm2;                 // r2in == 0: members are above-bucket only
        sK = keys[0] - 1ull;       // strictly below best bucket key
    }
    __syncthreads();
    if (r2in > 0 && t == (r2in - 1) / IT) {
        double cum = cm2 + base;
#pragma unroll
        for (int i = 0; i < IT; i++) {
            int r = t * IT + i;
            if (r < bcnt && r <= r2in - 1) {
                cum += (double)key_p(keys[i]);
                if (r == r2in - 1) { sS2 = cum; sK = keys[i]; }
            }
        }
    }
    __syncthreads();
    if (t == 0) {
        g_S2f[b] = (float)sS2;
        g_kstar[b] = sK;
    }
}

// role-1 post-sort: filters + inverse-CDF sample; writes token + sampkey.
template <int IT>
__device__ void role1_post(ull (&keys)[IT], int hcnt, float invf, float p1,
                           float thr, const int* topks, const float* uu,
                           float* out, int b, double* sh_d, int* sh_i) {
    __shared__ int   s_rf, s_s;
    __shared__ float s_total, s_target;
    const int t = threadIdx.x;

    double loc = 0.0;
#pragma unroll
    for (int i = 0; i < IT; i++) {
        int r = t * IT + i;
        if (r < hcnt) loc += (double)key_p(keys[i]);
    }
    sh_d[t] = loc;
    __syncthreads();
    for (int o = 1; o < K2T; o <<= 1) {
        double v = (t >= o) ? sh_d[t - o] : 0.0;
        __syncthreads();
        sh_d[t] += v;
        __syncthreads();
    }
    const double base = (t > 0) ? sh_d[t - 1] : 0.0;

    int c1 = 0, cm = 0;
    {
        double cum = base;
#pragma unroll
        for (int i = 0; i < IT; i++) {
            int r = t * IT + i;
            if (r < hcnt) {
                float p = key_p(keys[i]);
                cum += (double)p;
                float cse = (float)cum;
                c1 += !((cse - p) > p1);
                cm += (p >= thr);
            }
        }
    }
    sh_i[t] = c1;
    __syncthreads();
    for (int o = K2T / 2; o > 0; o >>= 1) { if (t < o) sh_i[t] += sh_i[t + o]; __syncthreads(); }
    const int rp1 = sh_i[0];
    __syncthreads();
    sh_i[t] = cm;
    __syncthreads();
    for (int o = K2T / 2; o > 0; o >>= 1) { if (t < o) sh_i[t] += sh_i[t + o]; __syncthreads(); }
    const int rminp = sh_i[0];
    __syncthreads();

    if (t == 0) {
        int k = topks[b];
        if (k < 1) k = 1;
        if (k > SV) k = SV;
        int rf = min(min(k, rp1), rminp);
        if (rf < 1) rf = 1;
        if (rf > hcnt) rf = hcnt;
        s_rf = rf;
    }
    __syncthreads();
    const int rf = s_rf;

    if (t == (rf - 1) / IT) {
        double cum = base;
#pragma unroll
        for (int i = 0; i < IT; i++) {
            int r = t * IT + i;
            if (r <= rf - 1) {
                cum += (double)key_p(keys[i]);
                if (r == rf - 1) s_total = (float)cum;
            }
        }
    }
    __syncthreads();
    if (t == 0) s_target = uu[b] * s_total;
    __syncthreads();
    const float target = s_target;

    int cnt2 = 0;
    {
        double cum = base;
#pragma unroll
        for (int i = 0; i < IT; i++) {
            int r = t * IT + i;
            if (r < rf) {
                cum += (double)key_p(keys[i]);
                if ((float)cum < target) cnt2++;
            }
        }
    }
    sh_i[t] = cnt2;
    __syncthreads();
    for (int o = K2T / 2; o > 0; o >>= 1) { if (t < o) sh_i[t] += sh_i[t + o]; __syncthreads(); }
    if (t == 0) {
        int ss = sh_i[0];
        if (ss < 0) ss = 0;
        if (ss > SV - 1) ss = SV - 1;
        s_s = ss;
    }
    __syncthreads();
    const int ssel = s_s;

    if (t == ssel / IT) {
#pragma unroll
        for (int i = 0; i < IT; i++) {
            int r = t * IT + i;
            if (r == ssel) {
                ull kk = keys[i];
                out[b] = (float)key_idx(kk);   // token_ids
                g_sampkey[b] = kk;             // nlp computed in k3
            }
        }
    }
}

__global__ __launch_bounds__(K2T) void k2_kernel(
    const float* __restrict__ topps2,
    const int* __restrict__ topks,
    const float* __restrict__ topps,
    const float* __restrict__ minps,
    const float* __restrict__ uu,
    float* __restrict__ out) {
    extern __shared__ char dynsm[];
    SortTemp& stemp = *(SortTemp*)dynsm;
    __shared__ double sh_d[K2T];
    __shared__ int    sh_i[K2T];
    __shared__ ull    sh_u[K2T];

    const int role = blockIdx.x & 1;
    const int b = blockIdx.x >> 1;

    if (role == 0) {
        // ---------------- nucleus boundary ----------------
        const int bcnt = min(g_bcnt[b], B2CAP);
        const double cm2 = g_cm2[b];
        const float p2f = topps2[b];
        const ull* buf = &g_b2buf[(size_t)b * B2CAP];

        if (bcnt <= 2048) {
            ull keys[8];
            load_striped<8>(keys, buf, bcnt);
            sort_rebased<8>(keys, bcnt, stemp.a, sh_u);
            role0_post<8>(keys, bcnt, cm2, p2f, b, sh_d, sh_i);
        } else {
            ull keys[16];
            load_striped<16>(keys, buf, bcnt);
            sort_rebased<16>(keys, bcnt, stemp.c, sh_u);
            role0_post<16>(keys, bcnt, cm2, p2f, b, sh_d, sh_i);
        }
    } else {
        // ---------------- head sort + sampling ----------------
        const int hcnt = min(g_hcnt[b], HDCAP);
        const float invf = g_invf[b];
        const float p1 = topps[b];
        const float thr = invf * minps[b];   // ps[0] * min_p  (top e == 1.0)
        const ull* buf = &g_head[(size_t)b * HDCAP];

        if (hcnt <= 2560) {
            ull keys[10];
            load_striped<10>(keys, buf, hcnt);
            sort_rebased<10>(keys, hcnt, stemp.b, sh_u);
            role1_post<10>(keys, hcnt, invf, p1, thr, topks, uu, out, b, sh_d, sh_i);
        } else {
            ull keys[16];
            load_striped<16>(keys, buf, hcnt);
            sort_rebased<16>(keys, hcnt, stemp.c, sh_u);
            role1_post<16>(keys, hcnt, invf, p1, thr, topks, uu, out, b, sh_d, sh_i);
        }
    }
}

// ---------------------------------------------------------------------------
// K3: coalesced logprob matrix reading precomputed e; membership iff
// key <= Kstar.  Writes next_token_logprobs at q==0.  grid (125, SB) x 256.
// ---------------------------------------------------------------------------
__global__ __launch_bounds__(256) void k3_kernel(float* __restrict__ out) {
    const int b = blockIdx.y;
    const int q = blockIdx.x * 256 + threadIdx.x;   // 0..31999
    const float invf = g_invf[b];
    const float S2f = g_S2f[b];
    const ull Kst = g_kstar[b];
    const unsigned khi = (unsigned)(Kst >> 17);
    const unsigned klo = (unsigned)(Kst & 0x1FFFFull);

    const float4 e = ((const float4*)(g_work + (size_t)b * SV))[q];
    float ev[4] = {e.x, e.y, e.z, e.w};
    float ov[4];
#pragma unroll
    for (int c = 0; c < 4; c++) {
        float p = ev[c] * invf;
        unsigned pk = 0x7FFFFFFFu - __float_as_uint(p);
        bool mem = (pk < khi) || (pk == khi && (unsigned)(q * 4 + c) <= klo);
        ov[c] = mem ? fmaxf(logf(p / S2f), -FLT_MAX) : -FLT_MAX;
    }
    ((float4*)(out + (size_t)SB + (size_t)b * SV))[q] =
        make_float4(ov[0], ov[1], ov[2], ov[3]);

    if (q == 0) {
        ull kk = g_sampkey[b];
        float psf = key_p(kk);
        float nlp = (kk <= Kst) ? fmaxf(logf(psf / S2f), -FLT_MAX) : -FLT_MAX;
        out[(size_t)SB + (size_t)SB * SV + b] = nlp;
    }
}

// ---------------------------------------------------------------------------
// Host launcher (graph-capturable: kernel launches only)
// ---------------------------------------------------------------------------
extern "C" void kernel_launch(void* const* d_in, const int* in_sizes, int n_in,
                              void* d_out, int out_size) {
    const float* logits = (const float*)d_in[0];
    const float* temps  = (const float*)d_in[1];
    const int*   topks  = (const int*)d_in[2];
    const float* topps  = (const float*)d_in[3];
    const float* topps2 = (const float*)d_in[4];
    const float* minps  = (const float*)d_in[5];
    const float* u      = (const float*)d_in[6];
    float* out = (float*)d_out;

    const int sortBytes = (int)sizeof(SortTemp);
    cudaFuncSetAttribute(k2_kernel, cudaFuncAttributeMaxDynamicSharedMemorySize, sortBytes);

    dim3 g8(8, SB);
    k_max<<<g8, 512>>>(logits);
    k_exp<<<g8, 512>>>(logits, temps);
    k_gather<<<g8, 512>>>(topps2);
    k2_kernel<<<256, K2T, sortBytes>>>(topps2, topks, topps, minps, u, out);
    {
        dim3 g(SQ / 256, SB);
        k3_kernel<<<g, 256>>>(out);
    }
}

// round 13
// speedup vs baseline: 1.7929x; 1.7929x over previous
#include <cuda_runtime.h>
#include <cub/block/block_radix_sort.cuh>
#include <math.h>
#include <float.h>
#include <limits.h>
#include <stdint.h>

#define SB 128
#define SV 128000
#define SQ (SV / 4)            // 32000 float4 per row
#define B2CAP 4096             // crossing-bucket gather capacity
#define HDCAP 4096             // head gather capacity (top_ks <= 2047)
#define HEADN 2048
#define SKIPBITS 0x2B800000u   // e < 2^-40: skip histogram (dS <= 1.2e-7 rel)
#define MASK42 ((1ull << 42) - 1ull)
#define K2T 256
typedef unsigned long long ull;

// ---------------------------------------------------------------------------
// Static device scratch
// ---------------------------------------------------------------------------
__device__ float    g_work[(size_t)SB * SV];        // e = exp(x - M), 65.5 MB
__device__ ull      g_histpart[(size_t)SB * 8 * 1024];  // per-block hist partials
__device__ ull      g_head[(size_t)SB * HDCAP];
__device__ ull      g_b2buf[(size_t)SB * B2CAP];
__device__ float    g_maxpart[SB * 8];
__device__ int      g_hcnt[SB];
__device__ int      g_bcnt[SB];
__device__ float    g_invf[SB];              // f32(1/S) == ps[0]
__device__ double   g_cm2[SB];               // p-mass strictly above crossing bucket
__device__ float    g_S2f[SB];               // nucleus mass (f32)
__device__ ull      g_kstar[SB];             // largest member key
__device__ ull      g_sampkey[SB];           // sampled element's key

// key48: ascending == p descending, index ascending (stable argsort ties)
__device__ __forceinline__ ull make_key(unsigned pb, int idx) {
    return (((ull)(0x7FFFFFFFu - pb)) << 17) | (unsigned)idx;
}
__device__ __forceinline__ float key_p(ull k) {
    return __uint_as_float(0x7FFFFFFFu - (unsigned)(k >> 17));
}
__device__ __forceinline__ int key_idx(ull k) { return (int)(k & 0x1FFFFull); }

// M = f32(Lmax/T): division by T>0 is monotone, so max of f32(l/T) = f32(max l / T)
__device__ __forceinline__ float row_M(int b, float T) {
    float m = g_maxpart[b * 8];
#pragma unroll
    for (int j = 1; j < 8; j++) m = fmaxf(m, g_maxpart[b * 8 + j]);
    return m / T;
}

// warp-aggregated filtered append (all lanes must call)
__device__ __forceinline__ void wagg_append(bool pred, ull key, int* cnt,
                                            ull* buf, int cap) {
    unsigned m = __ballot_sync(0xFFFFFFFFu, pred);
    if (m == 0) return;
    const int lane = threadIdx.x & 31;
    const int leader = __ffs(m) - 1;
    int pos0 = 0;
    if (lane == leader) pos0 = atomicAdd(cnt, __popc(m));
    pos0 = __shfl_sync(0xFFFFFFFFu, pos0, leader);
    if (pred) {
        int pos = pos0 + __popc(m & ((1u << lane) - 1u));
        if (pos < cap) buf[pos] = key;
    }
}

// ---------------------------------------------------------------------------
// K_max: per-row max of RAW logits + zero counters.  grid (8, SB) x 512.
// ---------------------------------------------------------------------------
__global__ __launch_bounds__(512) void k_max(const float* __restrict__ logits) {
    __shared__ float sf[512];
    const int b = blockIdx.y;
    const int bx = blockIdx.x;
    if (bx == 0 && threadIdx.x == 0) { g_hcnt[b] = 0; g_bcnt[b] = 0; }

    const float4* row = (const float4*)(logits + (size_t)b * SV);
    float m = -FLT_MAX;
#pragma unroll
    for (int j = 0; j < 8; j++) {
        int q = j * 4096 + bx * 512 + threadIdx.x;
        if (q < SQ) {
            float4 v = row[q];
            m = fmaxf(m, fmaxf(fmaxf(v.x, v.y), fmaxf(v.z, v.w)));
        }
    }
    sf[threadIdx.x] = m;
    __syncthreads();
    for (int o = 256; o > 0; o >>= 1) {
        if (threadIdx.x < o) sf[threadIdx.x] = fmaxf(sf[threadIdx.x], sf[threadIdx.x + o]);
        __syncthreads();
    }
    if (threadIdx.x == 0) g_maxpart[b * 8 + bx] = sf[0];
}

// ---------------------------------------------------------------------------
// K_exp: e = expf(l/T - M) -> g_work; exact packed smem histogram
// (count<<42 | sig24) with PLAIN smem atomics (measured at the ATOMS floor;
// warp-aggregation via match/redux measured SLOWER).  grid (8, SB) x 512.
// ---------------------------------------------------------------------------
__global__ __launch_bounds__(512) void k_exp(const float* __restrict__ logits,
                                             const float* __restrict__ temps) {
    __shared__ ull hist[1024];
    hist[threadIdx.x] = 0ull;
    hist[threadIdx.x + 512] = 0ull;
    const int b = blockIdx.y;
    const float T = temps[b];
    const float M = row_M(b, T);
    const float4* row = (const float4*)(logits + (size_t)b * SV);
    float4* erow = (float4*)(g_work + (size_t)b * SV);
    __syncthreads();
#pragma unroll
    for (int j = 0; j < 8; j++) {
        int q = j * 4096 + blockIdx.x * 512 + threadIdx.x;
        if (q < SQ) {
            float4 l = row[q];
            float4 e;
            e.x = expf(l.x / T - M);
            e.y = expf(l.y / T - M);
            e.z = expf(l.z / T - M);
            e.w = expf(l.w / T - M);
            erow[q] = e;
            unsigned eb;
            eb = __float_as_uint(e.x);
            if (eb >= SKIPBITS)
                atomicAdd(&hist[eb >> 20], (1ull << 42) | (ull)((eb & 0x7FFFFFu) | 0x800000u));
            eb = __float_as_uint(e.y);
            if (eb >= SKIPBITS)
                atomicAdd(&hist[eb >> 20], (1ull << 42) | (ull)((eb & 0x7FFFFFu) | 0x800000u));
            eb = __float_as_uint(e.z);
            if (eb >= SKIPBITS)
                atomicAdd(&hist[eb >> 20], (1ull << 42) | (ull)((eb & 0x7FFFFFu) | 0x800000u));
            eb = __float_as_uint(e.w);
            if (eb >= SKIPBITS)
                atomicAdd(&hist[eb >> 20], (1ull << 42) | (ull)((eb & 0x7FFFFFu) | 0x800000u));
        }
    }
    __syncthreads();
    ull* outp = &g_histpart[((size_t)(b * 8 + blockIdx.x)) << 10];
    outp[threadIdx.x] = hist[threadIdx.x];
    outp[threadIdx.x + 512] = hist[threadIdx.x + 512];
}

// ---------------------------------------------------------------------------
// K_gather: merge 8 hist partials; suffix scans -> S, invf, Bk, B2, cm2;
// then gather head + crossing-bucket keys reading precomputed e (g_work).
// grid (8, SB) x 512.
// ---------------------------------------------------------------------------
__global__ __launch_bounds__(512) void k_gather(const float* __restrict__ topps2) {
    __shared__ int    sh_i[1024];
    __shared__ double sh_d[1024];
    __shared__ int    s_B2, s_minb, s_Bk;
    __shared__ double s_cm2;

    const int b = blockIdx.y;
    const int bx = blockIdx.x;
    const int t = threadIdx.x;

    if (t == 0) { s_B2 = -1; s_minb = 1024; s_Bk = 0; }

    // ---- merge partials (identical in every block; 64KB L2 read) ----
    ull h0 = 0ull, h1 = 0ull;
#pragma unroll
    for (int j = 0; j < 8; j++) {
        const ull* p = &g_histpart[((size_t)(b * 8 + j)) << 10];
        h0 += p[t];
        h1 += p[512 + t];
    }
    const int c0 = (int)(h0 >> 42), c1i = (int)(h1 >> 42);
    sh_i[t] = c0;
    sh_i[512 + t] = c1i;
    sh_d[t] = ldexp((double)(h0 & MASK42), (t >> 3) - 150);
    sh_d[512 + t] = ldexp((double)(h1 & MASK42), ((512 + t) >> 3) - 150);
    __syncthreads();
    // suffix inclusive scans (toward higher bucket == higher p)
    for (int o = 1; o < 1024; o <<= 1) {
        int iv0 = 0, iv1 = 0; double dv0 = 0.0, dv1 = 0.0;
        if (t + o < 1024) { iv0 = sh_i[t + o]; dv0 = sh_d[t + o]; }
        if (512 + t + o < 1024) { iv1 = sh_i[512 + t + o]; dv1 = sh_d[512 + t + o]; }
        __syncthreads();
        sh_i[t] += iv0; sh_d[t] += dv0;
        sh_i[512 + t] += iv1; sh_d[512 + t] += dv1;
        __syncthreads();
    }
    const double S = sh_d[0];
    const double p2S = (double)topps2[b] * S;
    const float invf = (float)(1.0 / S);

    // selection at both owned positions
    {
        const int poss[2] = {t, 512 + t};
        const int cnts[2] = {c0, c1i};
#pragma unroll
        for (int z = 0; z < 2; z++) {
            const int pos = poss[z], cnt = cnts[z];
            const int    ccincl = sh_i[pos];
            const int    ccnext = (pos < 1023) ? sh_i[pos + 1] : 0;
            const double cmincl = sh_d[pos];
            const double cmnext = (pos < 1023) ? sh_d[pos + 1] : 0.0;
            if (ccincl >= HEADN && ccnext < HEADN) s_Bk = pos;
            if (cnt > 0) {
                atomicMin(&s_minb, pos);
                if (cmnext <= p2S && cmincl > p2S) { s_B2 = pos; s_cm2 = cmnext; }
            }
        }
    }
    __syncthreads();
    if (s_B2 < 0) {
        if (t == s_minb) { s_B2 = t; s_cm2 = (t < 1023) ? sh_d[t + 1] : 0.0; }
        else if (512 + t == s_minb) { s_B2 = 512 + t; s_cm2 = (512 + t < 1023) ? sh_d[513 + t] : 0.0; }
    }
    __syncthreads();
    const int B2 = s_B2, Bk = s_Bk;
    if (bx == 0 && t == 0) {
        g_invf[b] = invf;
        g_cm2[b] = s_cm2 / S;     // p-units mass strictly above crossing bucket
    }

    // ---- gather both lists from precomputed e ----
    const unsigned thk  = ((unsigned)Bk) << 20;
    const unsigned b2lo = ((unsigned)B2) << 20;
    const unsigned b2hi = b2lo + (1u << 20);
    const float4* row4 = (const float4*)(g_work + (size_t)b * SV);
    ull* hb = &g_head[(size_t)b * HDCAP];
    ull* bb = &g_b2buf[(size_t)b * B2CAP];
#pragma unroll
    for (int j = 0; j < 8; j++) {
        int q = j * 4096 + bx * 512 + t;
        bool valid = (q < SQ);
        float4 e = valid ? row4[q] : make_float4(0.f, 0.f, 0.f, 0.f);
        float ev[4] = {e.x, e.y, e.z, e.w};
#pragma unroll
        for (int c = 0; c < 4; c++) {
            unsigned eb = __float_as_uint(ev[c]);
            bool hh = valid && (eb >= thk);
            bool b2p = valid && (eb >= b2lo) && (eb < b2hi);
            ull key = 0ull;
            if (hh || b2p) key = make_key(__float_as_uint(ev[c] * invf), q * 4 + c);
            wagg_append(hh, key, &g_hcnt[b], hb, HDCAP);
            wagg_append(b2p, key, &g_bcnt[b], bb, B2CAP);
        }
    }
}

// ---------------------------------------------------------------------------
// K2: 256 blocks x 256 threads (measured 32.7us in R11).
//   role 0: crossing-bucket sort + f32 boundary walk -> Kstar, S2
//   role 1: head sort + filters + inverse-CDF sample -> token, sampkey
// Size-adaptive sorters (8/10/16 items) + runtime key rebasing.
// ---------------------------------------------------------------------------
typedef cub::BlockRadixSort<ull, K2T, 8>  SorterA;   // 2048
typedef cub::BlockRadixSort<ull, K2T, 10> SorterB;   // 2560
typedef cub::BlockRadixSort<ull, K2T, 16> SorterC;   // 4096 fallback
union SortTemp {
    SorterA::TempStorage a;
    SorterB::TempStorage b;
    SorterC::TempStorage c;
};

__device__ __forceinline__ ull blk_min(ull v, ull* sh) {
    const int t = threadIdx.x;
    sh[t] = v; __syncthreads();
    for (int o = K2T / 2; o > 0; o >>= 1) {
        if (t < o) sh[t] = min(sh[t], sh[t + o]);
        __syncthreads();
    }
    ull r = sh[0]; __syncthreads();
    return r;
}
__device__ __forceinline__ ull blk_max(ull v, ull* sh) {
    const int t = threadIdx.x;
    sh[t] = v; __syncthreads();
    for (int o = K2T / 2; o > 0; o >>= 1) {
        if (t < o) sh[t] = max(sh[t], sh[t + o]);
        __syncthreads();
    }
    ull r = sh[0]; __syncthreads();
    return r;
}

template <int IT>
__device__ __forceinline__ void load_striped(ull (&keys)[IT], const ull* buf, int n) {
    const int t = threadIdx.x;
#pragma unroll
    for (int i = 0; i < IT; i++) {
        int r = i * K2T + t;
        keys[i] = (r < n) ? buf[r] : ~0ull;
    }
}

// rebase -> sort -> unrebase.  Input striped, output blocked (sorted).
template <int IT, class TS>
__device__ void sort_rebased(ull (&keys)[IT], int n, TS& ts, ull* sh_u) {
    const int t = threadIdx.x;
    ull vmin = ~0ull, vmax = 0ull;
#pragma unroll
    for (int i = 0; i < IT; i++) {
        int r = i * K2T + t;
        if (r < n) { vmin = min(vmin, keys[i]); vmax = max(vmax, keys[i]); }
    }
    const ull kmin = blk_min(vmin, sh_u);
    const ull kmax = blk_max(vmax, sh_u);
    const ull kbase = kmin & ~0x1FFFFull;
    const int endbit = 64 - __clzll((long long)((kmax - kbase) | 1ull));
#pragma unroll
    for (int i = 0; i < IT; i++) {
        int r = i * K2T + t;
        if (r < n) keys[i] -= kbase;
    }
    cub::BlockRadixSort<ull, K2T, IT>(ts).Sort(keys, 0, endbit);
    __syncthreads();
#pragma unroll
    for (int i = 0; i < IT; i++) {
        int r = t * IT + i;
        if (r < n) keys[i] += kbase;
    }
}

// role-0 post-sort: double prefix + f32 boundary walk; writes Kstar, S2.
template <int IT>
__device__ void role0_post(ull (&keys)[IT], int bcnt, double cm2, float p2f,
                           int b, double* sh_d, int* sh_i) {
    __shared__ double sS2;
    __shared__ ull    sK;
    const int t = threadIdx.x;

    double loc = 0.0;
#pragma unroll
    for (int i = 0; i < IT; i++) {
        int r = t * IT + i;
        if (r < bcnt) loc += (double)key_p(keys[i]);
    }
    sh_d[t] = loc;
    __syncthreads();
    for (int o = 1; o < K2T; o <<= 1) {
        double v = (t >= o) ? sh_d[t - o] : 0.0;
        __syncthreads();
        sh_d[t] += v;
        __syncthreads();
    }
    const double base = (t > 0) ? sh_d[t - 1] : 0.0;

    int ff = INT_MAX;
    {
        double cum = cm2 + base;
#pragma unroll
        for (int i = 0; i < IT; i++) {
            int r = t * IT + i;
            if (r < bcnt) {
                float p = key_p(keys[i]);
                cum += (double)p;
                float cse = (float)cum;
                if (cse - p > p2f && r < ff) ff = r;
            }
        }
    }
    sh_i[t] = ff;
    __syncthreads();
    for (int o = K2T / 2; o > 0; o >>= 1) {
        if (t < o) sh_i[t] = min(sh_i[t], sh_i[t + o]);
        __syncthreads();
    }
    const int r2in = min(sh_i[0], bcnt);

    if (t == 0) {
        sS2 = cm2;                 // r2in == 0: members are above-bucket only
        sK = keys[0] - 1ull;       // strictly below best bucket key
    }
    __syncthreads();
    if (r2in > 0 && t == (r2in - 1) / IT) {
        double cum = cm2 + base;
#pragma unroll
        for (int i = 0; i < IT; i++) {
            int r = t * IT + i;
            if (r < bcnt && r <= r2in - 1) {
                cum += (double)key_p(keys[i]);
                if (r == r2in - 1) { sS2 = cum; sK = keys[i]; }
            }
        }
    }
    __syncthreads();
    if (t == 0) {
        g_S2f[b] = (float)sS2;
        g_kstar[b] = sK;
    }
}

// role-1 post-sort: filters + inverse-CDF sample; writes token + sampkey.
template <int IT>
__device__ void role1_post(ull (&keys)[IT], int hcnt, float invf, float p1,
                           float thr, const int* topks, const float* uu,
                           float* out, int b, double* sh_d, int* sh_i) {
    __shared__ int   s_rf, s_s;
    __shared__ float s_total, s_target;
    const int t = threadIdx.x;

    double loc = 0.0;
#pragma unroll
    for (int i = 0; i < IT; i++) {
        int r = t * IT + i;
        if (r < hcnt) loc += (double)key_p(keys[i]);
    }
    sh_d[t] = loc;
    __syncthreads();
    for (int o = 1; o < K2T; o <<= 1) {
        double v = (t >= o) ? sh_d[t - o] : 0.0;
        __syncthreads();
        sh_d[t] += v;
        __syncthreads();
    }
    const double base = (t > 0) ? sh_d[t - 1] : 0.0;

    int c1 = 0, cm = 0;
    {
        double cum = base;
#pragma unroll
        for (int i = 0; i < IT; i++) {
            int r = t * IT + i;
            if (r < hcnt) {
                float p = key_p(keys[i]);
                cum += (double)p;
                float cse = (float)cum;
                c1 += !((cse - p) > p1);
                cm += (p >= thr);
            }
        }
    }
    sh_i[t] = c1;
    __syncthreads();
    for (int o = K2T / 2; o > 0; o >>= 1) { if (t < o) sh_i[t] += sh_i[t + o]; __syncthreads(); }
    const int rp1 = sh_i[0];
    __syncthreads();
    sh_i[t] = cm;
    __syncthreads();
    for (int o = K2T / 2; o > 0; o >>= 1) { if (t < o) sh_i[t] += sh_i[t + o]; __syncthreads(); }
    const int rminp = sh_i[0];
    __syncthreads();

    if (t == 0) {
        int k = topks[b];
        if (k < 1) k = 1;
        if (k > SV) k = SV;
        int rf = min(min(k, rp1), rminp);
        if (rf < 1) rf = 1;
        if (rf > hcnt) rf = hcnt;
        s_rf = rf;
    }
    __syncthreads();
    const int rf = s_rf;

    if (t == (rf - 1) / IT) {
        double cum = base;
#pragma unroll
        for (int i = 0; i < IT; i++) {
            int r = t * IT + i;
            if (r <= rf - 1) {
                cum += (double)key_p(keys[i]);
                if (r == rf - 1) s_total = (float)cum;
            }
        }
    }
    __syncthreads();
    if (t == 0) s_target = uu[b] * s_total;
    __syncthreads();
    const float target = s_target;

    int cnt2 = 0;
    {
        double cum = base;
#pragma unroll
        for (int i = 0; i < IT; i++) {
            int r = t * IT + i;
            if (r < rf) {
                cum += (double)key_p(keys[i]);
                if ((float)cum < target) cnt2++;
            }
        }
    }
    sh_i[t] = cnt2;
    __syncthreads();
    for (int o = K2T / 2; o > 0; o >>= 1) { if (t < o) sh_i[t] += sh_i[t + o]; __syncthreads(); }
    if (t == 0) {
        int ss = sh_i[0];
        if (ss < 0) ss = 0;
        if (ss > SV - 1) ss = SV - 1;
        s_s = ss;
    }
    __syncthreads();
    const int ssel = s_s;

    if (t == ssel / IT) {
#pragma unroll
        for (int i = 0; i < IT; i++) {
            int r = t * IT + i;
            if (r == ssel) {
                ull kk = keys[i];
                out[b] = (float)key_idx(kk);   // token_ids
                g_sampkey[b] = kk;             // nlp computed in k3
            }
        }
    }
}

__global__ __launch_bounds__(K2T) void k2_kernel(
    const float* __restrict__ topps2,
    const int* __restrict__ topks,
    const float* __restrict__ topps,
    const float* __restrict__ minps,
    const float* __restrict__ uu,
    float* __restrict__ out) {
    extern __shared__ char dynsm[];
    SortTemp& stemp = *(SortTemp*)dynsm;
    __shared__ double sh_d[K2T];
    __shared__ int    sh_i[K2T];
    __shared__ ull    sh_u[K2T];

    const int role = blockIdx.x & 1;
    const int b = blockIdx.x >> 1;

    if (role == 0) {
        // ---------------- nucleus boundary ----------------
        const int bcnt = min(g_bcnt[b], B2CAP);
        const double cm2 = g_cm2[b];
        const float p2f = topps2[b];
        const ull* buf = &g_b2buf[(size_t)b * B2CAP];

        if (bcnt <= 2048) {
            ull keys[8];
            load_striped<8>(keys, buf, bcnt);
            sort_rebased<8>(keys, bcnt, stemp.a, sh_u);
            role0_post<8>(keys, bcnt, cm2, p2f, b, sh_d, sh_i);
        } else {
            ull keys[16];
            load_striped<16>(keys, buf, bcnt);
            sort_rebased<16>(keys, bcnt, stemp.c, sh_u);
            role0_post<16>(keys, bcnt, cm2, p2f, b, sh_d, sh_i);
        }
    } else {
        // ---------------- head sort + sampling ----------------
        const int hcnt = min(g_hcnt[b], HDCAP);
        const float invf = g_invf[b];
        const float p1 = topps[b];
        const float thr = invf * minps[b];   // ps[0] * min_p  (top e == 1.0)
        const ull* buf = &g_head[(size_t)b * HDCAP];

        if (hcnt <= 2560) {
            ull keys[10];
            load_striped<10>(keys, buf, hcnt);
            sort_rebased<10>(keys, hcnt, stemp.b, sh_u);
            role1_post<10>(keys, hcnt, invf, p1, thr, topks, uu, out, b, sh_d, sh_i);
        } else {
            ull keys[16];
            load_striped<16>(keys, buf, hcnt);
            sort_rebased<16>(keys, hcnt, stemp.c, sh_u);
            role1_post<16>(keys, hcnt, invf, p1, thr, topks, uu, out, b, sh_d, sh_i);
        }
    }
}

// ---------------------------------------------------------------------------
// K3: coalesced logprob matrix reading precomputed e; membership iff
// key <= Kstar.  Writes next_token_logprobs at q==0.  grid (125, SB) x 256.
// ---------------------------------------------------------------------------
__global__ __launch_bounds__(256) void k3_kernel(float* __restrict__ out) {
    const int b = blockIdx.y;
    const int q = blockIdx.x * 256 + threadIdx.x;   // 0..31999
    const float invf = g_invf[b];
    const float S2f = g_S2f[b];
    const ull Kst = g_kstar[b];
    const unsigned khi = (unsigned)(Kst >> 17);
    const unsigned klo = (unsigned)(Kst & 0x1FFFFull);

    const float4 e = ((const float4*)(g_work + (size_t)b * SV))[q];
    float ev[4] = {e.x, e.y, e.z, e.w};
    float ov[4];
#pragma unroll
    for (int c = 0; c < 4; c++) {
        float p = ev[c] * invf;
        unsigned pk = 0x7FFFFFFFu - __float_as_uint(p);
        bool mem = (pk < khi) || (pk == khi && (unsigned)(q * 4 + c) <= klo);
        ov[c] = mem ? fmaxf(logf(p / S2f), -FLT_MAX) : -FLT_MAX;
    }
    ((float4*)(out + (size_t)SB + (size_t)b * SV))[q] =
        make_float4(ov[0], ov[1], ov[2], ov[3]);

    if (q == 0) {
        ull kk = g_sampkey[b];
        float psf = key_p(kk);
        float nlp = (kk <= Kst) ? fmaxf(logf(psf / S2f), -FLT_MAX) : -FLT_MAX;
        out[(size_t)SB + (size_t)SB * SV + b] = nlp;
    }
}

// ---------------------------------------------------------------------------
// Host launcher (graph-capturable: kernel launches only)
// ---------------------------------------------------------------------------
extern "C" void kernel_launch(void* const* d_in, const int* in_sizes, int n_in,
                              void* d_out, int out_size) {
    const float* logits = (const float*)d_in[0];
    const float* temps  = (const float*)d_in[1];
    const int*   topks  = (const int*)d_in[2];
    const float* topps  = (const float*)d_in[3];
    const float* topps2 = (const float*)d_in[4];
    const float* minps  = (const float*)d_in[5];
    const float* u      = (const float*)d_in[6];
    float* out = (float*)d_out;

    const int sortBytes = (int)sizeof(SortTemp);
    cudaFuncSetAttribute(k2_kernel, cudaFuncAttributeMaxDynamicSharedMemorySize, sortBytes);

    dim3 g8(8, SB);
    k_max<<<g8, 512>>>(logits);
    k_exp<<<g8, 512>>>(logits, temps);
    k_gather<<<g8, 512>>>(topps2);
    k2_kernel<<<256, K2T, sortBytes>>>(topps2, topks, topps, minps, u, out);
    {
        dim3 g(SQ / 256, SB);
        k3_kernel<<<g, 256>>>(out);
    }
}

// round 14
// speedup vs baseline: 1.8289x; 1.0201x over previous
#include <cuda_runtime.h>
#include <cub/block/block_radix_sort.cuh>
#include <math.h>
#include <float.h>
#include <limits.h>
#include <stdint.h>

#define SB 128
#define SV 128000
#define SQ (SV / 4)            // 32000 float4 per row
#define B2CAP 4096             // crossing-bucket gather capacity
#define HDCAP 4096             // head gather capacity (top_ks <= 2047)
#define HEADN 2048
#define SKIPBITS 0x2B800000u   // e < 2^-40: skip histogram (dS <= 1.2e-7 rel)
#define MASK42 ((1ull << 42) - 1ull)
#define K2T 256
typedef unsigned long long ull;

// ---------------------------------------------------------------------------
// Static device scratch
// ---------------------------------------------------------------------------
__device__ float    g_work[(size_t)SB * SV];        // e = exp(x - M), 65.5 MB
__device__ ull      g_histpart[(size_t)SB * 8 * 1024];  // per-block hist partials
__device__ ull      g_head[(size_t)SB * HDCAP];
__device__ ull      g_b2buf[(size_t)SB * B2CAP];
__device__ float    g_maxpart[SB * 8];
__device__ int      g_hcnt[SB];
__device__ int      g_bcnt[SB];
__device__ float    g_invf[SB];              // f32(1/S) == ps[0]
__device__ double   g_cm2[SB];               // p-mass strictly above crossing bucket
__device__ float    g_S2f[SB];               // nucleus mass (f32)
__device__ ull      g_kstar[SB];             // largest member key
__device__ ull      g_sampkey[SB];           // sampled element's key

// key48: ascending == p descending, index ascending (stable argsort ties)
__device__ __forceinline__ ull make_key(unsigned pb, int idx) {
    return (((ull)(0x7FFFFFFFu - pb)) << 17) | (unsigned)idx;
}
__device__ __forceinline__ float key_p(ull k) {
    return __uint_as_float(0x7FFFFFFFu - (unsigned)(k >> 17));
}
__device__ __forceinline__ int key_idx(ull k) { return (int)(k & 0x1FFFFull); }

// row max of RAW logits (merged from 8 per-block partials)
__device__ __forceinline__ float row_maxl(int b) {
    float m = g_maxpart[b * 8];
#pragma unroll
    for (int j = 1; j < 8; j++) m = fmaxf(m, g_maxpart[b * 8 + j]);
    return m;
}

// warp-aggregated filtered append (all lanes must call)
__device__ __forceinline__ void wagg_append(bool pred, ull key, int* cnt,
                                            ull* buf, int cap) {
    unsigned m = __ballot_sync(0xFFFFFFFFu, pred);
    if (m == 0) return;
    const int lane = threadIdx.x & 31;
    const int leader = __ffs(m) - 1;
    int pos0 = 0;
    if (lane == leader) pos0 = atomicAdd(cnt, __popc(m));
    pos0 = __shfl_sync(0xFFFFFFFFu, pos0, leader);
    if (pred) {
        int pos = pos0 + __popc(m & ((1u << lane) - 1u));
        if (pos < cap) buf[pos] = key;
    }
}

// ---------------------------------------------------------------------------
// K_max: per-row max of RAW logits + zero counters.  grid (8, SB) x 512.
// ---------------------------------------------------------------------------
__global__ __launch_bounds__(512) void k_max(const float* __restrict__ logits) {
    __shared__ float sf[512];
    const int b = blockIdx.y;
    const int bx = blockIdx.x;
    if (bx == 0 && threadIdx.x == 0) { g_hcnt[b] = 0; g_bcnt[b] = 0; }

    const float4* row = (const float4*)(logits + (size_t)b * SV);
    float m = -FLT_MAX;
#pragma unroll
    for (int j = 0; j < 8; j++) {
        int q = j * 4096 + bx * 512 + threadIdx.x;
        if (q < SQ) {
            float4 v = row[q];
            m = fmaxf(m, fmaxf(fmaxf(v.x, v.y), fmaxf(v.z, v.w)));
        }
    }
    sf[threadIdx.x] = m;
    __syncthreads();
    for (int o = 256; o > 0; o >>= 1) {
        if (threadIdx.x < o) sf[threadIdx.x] = fmaxf(sf[threadIdx.x], sf[threadIdx.x + o]);
        __syncthreads();
    }
    if (threadIdx.x == 0) g_maxpart[b * 8 + bx] = sf[0];
}

// ---------------------------------------------------------------------------
// K_exp: e = __expf(l*invT - M) -> g_work (x = l*invT is monotone in l, so
// M = maxl*invT is the exact row max of x); exact packed smem histogram
// (count<<42 | sig24) with plain smem atomics.  grid (8, SB) x 512.
// ---------------------------------------------------------------------------
__global__ __launch_bounds__(512) void k_exp(const float* __restrict__ logits,
                                             const float* __restrict__ temps) {
    __shared__ ull hist[1024];
    hist[threadIdx.x] = 0ull;
    hist[threadIdx.x + 512] = 0ull;
    const int b = blockIdx.y;
    const float invT = 1.0f / temps[b];
    const float M = row_maxl(b) * invT;
    const float4* row = (const float4*)(logits + (size_t)b * SV);
    float4* erow = (float4*)(g_work + (size_t)b * SV);
    __syncthreads();
#pragma unroll
    for (int j = 0; j < 8; j++) {
        int q = j * 4096 + blockIdx.x * 512 + threadIdx.x;
        if (q < SQ) {
            float4 l = row[q];
            float4 e;
            e.x = __expf(fmaf(l.x, invT, -M));
            e.y = __expf(fmaf(l.y, invT, -M));
            e.z = __expf(fmaf(l.z, invT, -M));
            e.w = __expf(fmaf(l.w, invT, -M));
            e.x = fminf(e.x, 1.0f);
            e.y = fminf(e.y, 1.0f);
            e.z = fminf(e.z, 1.0f);
            e.w = fminf(e.w, 1.0f);
            erow[q] = e;
            unsigned eb;
            eb = __float_as_uint(e.x);
            if (eb >= SKIPBITS)
                atomicAdd(&hist[eb >> 20], (1ull << 42) | (ull)((eb & 0x7FFFFFu) | 0x800000u));
            eb = __float_as_uint(e.y);
            if (eb >= SKIPBITS)
                atomicAdd(&hist[eb >> 20], (1ull << 42) | (ull)((eb & 0x7FFFFFu) | 0x800000u));
            eb = __float_as_uint(e.z);
            if (eb >= SKIPBITS)
                atomicAdd(&hist[eb >> 20], (1ull << 42) | (ull)((eb & 0x7FFFFFu) | 0x800000u));
            eb = __float_as_uint(e.w);
            if (eb >= SKIPBITS)
                atomicAdd(&hist[eb >> 20], (1ull << 42) | (ull)((eb & 0x7FFFFFu) | 0x800000u));
        }
    }
    __syncthreads();
    ull* outp = &g_histpart[((size_t)(b * 8 + blockIdx.x)) << 10];
    outp[threadIdx.x] = hist[threadIdx.x];
    outp[threadIdx.x + 512] = hist[threadIdx.x + 512];
}

// ---------------------------------------------------------------------------
// K_gather: merge 8 hist partials; suffix scans -> S, invf, Bk, B2, cm2;
// then gather head + crossing-bucket keys reading precomputed e (g_work).
// grid (8, SB) x 512.
// ---------------------------------------------------------------------------
__global__ __launch_bounds__(512) void k_gather(const float* __restrict__ topps2) {
    __shared__ int    sh_i[1024];
    __shared__ double sh_d[1024];
    __shared__ int    s_B2, s_minb, s_Bk;
    __shared__ double s_cm2;

    const int b = blockIdx.y;
    const int bx = blockIdx.x;
    const int t = threadIdx.x;

    if (t == 0) { s_B2 = -1; s_minb = 1024; s_Bk = 0; }

    // ---- merge partials (identical in every block; 64KB L2 read) ----
    ull h0 = 0ull, h1 = 0ull;
#pragma unroll
    for (int j = 0; j < 8; j++) {
        const ull* p = &g_histpart[((size_t)(b * 8 + j)) << 10];
        h0 += p[t];
        h1 += p[512 + t];
    }
    const int c0 = (int)(h0 >> 42), c1i = (int)(h1 >> 42);
    sh_i[t] = c0;
    sh_i[512 + t] = c1i;
    sh_d[t] = ldexp((double)(h0 & MASK42), (t >> 3) - 150);
    sh_d[512 + t] = ldexp((double)(h1 & MASK42), ((512 + t) >> 3) - 150);
    __syncthreads();
    // suffix inclusive scans (toward higher bucket == higher p)
    for (int o = 1; o < 1024; o <<= 1) {
        int iv0 = 0, iv1 = 0; double dv0 = 0.0, dv1 = 0.0;
        if (t + o < 1024) { iv0 = sh_i[t + o]; dv0 = sh_d[t + o]; }
        if (512 + t + o < 1024) { iv1 = sh_i[512 + t + o]; dv1 = sh_d[512 + t + o]; }
        __syncthreads();
        sh_i[t] += iv0; sh_d[t] += dv0;
        sh_i[512 + t] += iv1; sh_d[512 + t] += dv1;
        __syncthreads();
    }
    const double S = sh_d[0];
    const double p2S = (double)topps2[b] * S;
    const float invf = (float)(1.0 / S);

    // selection at both owned positions
    {
        const int poss[2] = {t, 512 + t};
        const int cnts[2] = {c0, c1i};
#pragma unroll
        for (int z = 0; z < 2; z++) {
            const int pos = poss[z], cnt = cnts[z];
            const int    ccincl = sh_i[pos];
            const int    ccnext = (pos < 1023) ? sh_i[pos + 1] : 0;
            const double cmincl = sh_d[pos];
            const double cmnext = (pos < 1023) ? sh_d[pos + 1] : 0.0;
            if (ccincl >= HEADN && ccnext < HEADN) s_Bk = pos;
            if (cnt > 0) {
                atomicMin(&s_minb, pos);
                if (cmnext <= p2S && cmincl > p2S) { s_B2 = pos; s_cm2 = cmnext; }
            }
        }
    }
    __syncthreads();
    if (s_B2 < 0) {
        if (t == s_minb) { s_B2 = t; s_cm2 = (t < 1023) ? sh_d[t + 1] : 0.0; }
        else if (512 + t == s_minb) { s_B2 = 512 + t; s_cm2 = (512 + t < 1023) ? sh_d[513 + t] : 0.0; }
    }
    __syncthreads();
    const int B2 = s_B2, Bk = s_Bk;
    if (bx == 0 && t == 0) {
        g_invf[b] = invf;
        g_cm2[b] = s_cm2 / S;     // p-units mass strictly above crossing bucket
    }

    // ---- gather both lists from precomputed e ----
    const unsigned thk  = ((unsigned)Bk) << 20;
    const unsigned b2lo = ((unsigned)B2) << 20;
    const unsigned b2hi = b2lo + (1u << 20);
    const float4* row4 = (const float4*)(g_work + (size_t)b * SV);
    ull* hb = &g_head[(size_t)b * HDCAP];
    ull* bb = &g_b2buf[(size_t)b * B2CAP];
#pragma unroll
    for (int j = 0; j < 8; j++) {
        int q = j * 4096 + bx * 512 + t;
        bool valid = (q < SQ);
        float4 e = valid ? row4[q] : make_float4(0.f, 0.f, 0.f, 0.f);
        float ev[4] = {e.x, e.y, e.z, e.w};
#pragma unroll
        for (int c = 0; c < 4; c++) {
            unsigned eb = __float_as_uint(ev[c]);
            bool hh = valid && (eb >= thk);
            bool b2p = valid && (eb >= b2lo) && (eb < b2hi);
            // skip both appends when the whole warp has no candidates
            if (__ballot_sync(0xFFFFFFFFu, hh || b2p)) {
                ull key = 0ull;
                if (hh || b2p) key = make_key(__float_as_uint(ev[c] * invf), q * 4 + c);
                wagg_append(hh, key, &g_hcnt[b], hb, HDCAP);
                wagg_append(b2p, key, &g_bcnt[b], bb, B2CAP);
            }
        }
    }
}

// ---------------------------------------------------------------------------
// K2: 256 blocks x 256 threads (measured 32.7us).
//   role 0: crossing-bucket sort + f32 boundary walk -> Kstar, S2
//   role 1: head sort + filters + inverse-CDF sample -> token, sampkey
// Size-adaptive sorters (8/10/16 items) + runtime key rebasing.
// ---------------------------------------------------------------------------
typedef cub::BlockRadixSort<ull, K2T, 8>  SorterA;   // 2048
typedef cub::BlockRadixSort<ull, K2T, 10> SorterB;   // 2560
typedef cub::BlockRadixSort<ull, K2T, 16> SorterC;   // 4096 fallback
union SortTemp {
    SorterA::TempStorage a;
    SorterB::TempStorage b;
    SorterC::TempStorage c;
};

__device__ __forceinline__ ull blk_min(ull v, ull* sh) {
    const int t = threadIdx.x;
    sh[t] = v; __syncthreads();
    for (int o = K2T / 2; o > 0; o >>= 1) {
        if (t < o) sh[t] = min(sh[t], sh[t + o]);
        __syncthreads();
    }
    ull r = sh[0]; __syncthreads();
    return r;
}
__device__ __forceinline__ ull blk_max(ull v, ull* sh) {
    const int t = threadIdx.x;
    sh[t] = v; __syncthreads();
    for (int o = K2T / 2; o > 0; o >>= 1) {
        if (t < o) sh[t] = max(sh[t], sh[t + o]);
        __syncthreads();
    }
    ull r = sh[0]; __syncthreads();
    return r;
}

template <int IT>
__device__ __forceinline__ void load_striped(ull (&keys)[IT], const ull* buf, int n) {
    const int t = threadIdx.x;
#pragma unroll
    for (int i = 0; i < IT; i++) {
        int r = i * K2T + t;
        keys[i] = (r < n) ? buf[r] : ~0ull;
    }
}

// rebase -> sort -> unrebase.  Input striped, output blocked (sorted).
template <int IT, class TS>
__device__ void sort_rebased(ull (&keys)[IT], int n, TS& ts, ull* sh_u) {
    const int t = threadIdx.x;
    ull vmin = ~0ull, vmax = 0ull;
#pragma unroll
    for (int i = 0; i < IT; i++) {
        int r = i * K2T + t;
        if (r < n) { vmin = min(vmin, keys[i]); vmax = max(vmax, keys[i]); }
    }
    const ull kmin = blk_min(vmin, sh_u);
    const ull kmax = blk_max(vmax, sh_u);
    const ull kbase = kmin & ~0x1FFFFull;
    const int endbit = 64 - __clzll((long long)((kmax - kbase) | 1ull));
#pragma unroll
    for (int i = 0; i < IT; i++) {
        int r = i * K2T + t;
        if (r < n) keys[i] -= kbase;
    }
    cub::BlockRadixSort<ull, K2T, IT>(ts).Sort(keys, 0, endbit);
    __syncthreads();
#pragma unroll
    for (int i = 0; i < IT; i++) {
        int r = t * IT + i;
        if (r < n) keys[i] += kbase;
    }
}

// role-0 post-sort: double prefix + f32 boundary walk; writes Kstar, S2.
template <int IT>
__device__ void role0_post(ull (&keys)[IT], int bcnt, double cm2, float p2f,
                           int b, double* sh_d, int* sh_i) {
    __shared__ double sS2;
    __shared__ ull    sK;
    const int t = threadIdx.x;

    double loc = 0.0;
#pragma unroll
    for (int i = 0; i < IT; i++) {
        int r = t * IT + i;
        if (r < bcnt) loc += (double)key_p(keys[i]);
    }
    sh_d[t] = loc;
    __syncthreads();
    for (int o = 1; o < K2T; o <<= 1) {
        double v = (t >= o) ? sh_d[t - o] : 0.0;
        __syncthreads();
        sh_d[t] += v;
        __syncthreads();
    }
    const double base = (t > 0) ? sh_d[t - 1] : 0.0;

    int ff = INT_MAX;
    {
        double cum = cm2 + base;
#pragma unroll
        for (int i = 0; i < IT; i++) {
            int r = t * IT + i;
            if (r < bcnt) {
                float p = key_p(keys[i]);
                cum += (double)p;
                float cse = (float)cum;
                if (cse - p > p2f && r < ff) ff = r;
            }
        }
    }
    sh_i[t] = ff;
    __syncthreads();
    for (int o = K2T / 2; o > 0; o >>= 1) {
        if (t < o) sh_i[t] = min(sh_i[t], sh_i[t + o]);
        __syncthreads();
    }
    const int r2in = min(sh_i[0], bcnt);

    if (t == 0) {
        sS2 = cm2;                 // r2in == 0: members are above-bucket only
        sK = keys[0] - 1ull;       // strictly below best bucket key
    }
    __syncthreads();
    if (r2in > 0 && t == (r2in - 1) / IT) {
        double cum = cm2 + base;
#pragma unroll
        for (int i = 0; i < IT; i++) {
            int r = t * IT + i;
            if (r < bcnt && r <= r2in - 1) {
                cum += (double)key_p(keys[i]);
                if (r == r2in - 1) { sS2 = cum; sK = keys[i]; }
            }
        }
    }
    __syncthreads();
    if (t == 0) {
        g_S2f[b] = (float)sS2;
        g_kstar[b] = sK;
    }
}

// role-1 post-sort: filters + inverse-CDF sample; writes token + sampkey.
template <int IT>
__device__ void role1_post(ull (&keys)[IT], int hcnt, float invf, float p1,
                           float thr, const int* topks, const float* uu,
                           float* out, int b, double* sh_d, int* sh_i) {
    __shared__ int   s_rf, s_s;
    __shared__ float s_total, s_target;
    const int t = threadIdx.x;

    double loc = 0.0;
#pragma unroll
    for (int i = 0; i < IT; i++) {
        int r = t * IT + i;
        if (r < hcnt) loc += (double)key_p(keys[i]);
    }
    sh_d[t] = loc;
    __syncthreads();
    for (int o = 1; o < K2T; o <<= 1) {
        double v = (t >= o) ? sh_d[t - o] : 0.0;
        __syncthreads();
        sh_d[t] += v;
        __syncthreads();
    }
    const double base = (t > 0) ? sh_d[t - 1] : 0.0;

    int c1 = 0, cm = 0;
    {
        double cum = base;
#pragma unroll
        for (int i = 0; i < IT; i++) {
            int r = t * IT + i;
            if (r < hcnt) {
                float p = key_p(keys[i]);
                cum += (double)p;
                float cse = (float)cum;
                c1 += !((cse - p) > p1);
                cm += (p >= thr);
            }
        }
    }
    sh_i[t] = c1;
    __syncthreads();
    for (int o = K2T / 2; o > 0; o >>= 1) { if (t < o) sh_i[t] += sh_i[t + o]; __syncthreads(); }
    const int rp1 = sh_i[0];
    __syncthreads();
    sh_i[t] = cm;
    __syncthreads();
    for (int o = K2T / 2; o > 0; o >>= 1) { if (t < o) sh_i[t] += sh_i[t + o]; __syncthreads(); }
    const int rminp = sh_i[0];
    __syncthreads();

    if (t == 0) {
        int k = topks[b];
        if (k < 1) k = 1;
        if (k > SV) k = SV;
        int rf = min(min(k, rp1), rminp);
        if (rf < 1) rf = 1;
        if (rf > hcnt) rf = hcnt;
        s_rf = rf;
    }
    __syncthreads();
    const int rf = s_rf;

    if (t == (rf - 1) / IT) {
        double cum = base;
#pragma unroll
        for (int i = 0; i < IT; i++) {
            int r = t * IT + i;
            if (r <= rf - 1) {
                cum += (double)key_p(keys[i]);
                if (r == rf - 1) s_total = (float)cum;
            }
        }
    }
    __syncthreads();
    if (t == 0) s_target = uu[b] * s_total;
    __syncthreads();
    const float target = s_target;

    int cnt2 = 0;
    {
        double cum = base;
#pragma unroll
        for (int i = 0; i < IT; i++) {
            int r = t * IT + i;
            if (r < rf) {
                cum += (double)key_p(keys[i]);
                if ((float)cum < target) cnt2++;
            }
        }
    }
    sh_i[t] = cnt2;
    __syncthreads();
    for (int o = K2T / 2; o > 0; o >>= 1) { if (t < o) sh_i[t] += sh_i[t + o]; __syncthreads(); }
    if (t == 0) {
        int ss = sh_i[0];
        if (ss < 0) ss = 0;
        if (ss > SV - 1) ss = SV - 1;
        s_s = ss;
    }
    __syncthreads();
    const int ssel = s_s;

    if (t == ssel / IT) {
#pragma unroll
        for (int i = 0; i < IT; i++) {
            int r = t * IT + i;
            if (r == ssel) {
                ull kk = keys[i];
                out[b] = (float)key_idx(kk);   // token_ids
                g_sampkey[b] = kk;             // nlp computed in k3
            }
        }
    }
}

__global__ __launch_bounds__(K2T) void k2_kernel(
    const float* __restrict__ topps2,
    const int* __restrict__ topks,
    const float* __restrict__ topps,
    const float* __restrict__ minps,
    const float* __restrict__ uu,
    float* __restrict__ out) {
    extern __shared__ char dynsm[];
    SortTemp& stemp = *(SortTemp*)dynsm;
    __shared__ double sh_d[K2T];
    __shared__ int    sh_i[K2T];
    __shared__ ull    sh_u[K2T];

    const int role = blockIdx.x & 1;
    const int b = blockIdx.x >> 1;

    if (role == 0) {
        // ---------------- nucleus boundary ----------------
        const int bcnt = min(g_bcnt[b], B2CAP);
        const double cm2 = g_cm2[b];
        const float p2f = topps2[b];
        const ull* buf = &g_b2buf[(size_t)b * B2CAP];

        if (bcnt <= 2048) {
            ull keys[8];
            load_striped<8>(keys, buf, bcnt);
            sort_rebased<8>(keys, bcnt, stemp.a, sh_u);
            role0_post<8>(keys, bcnt, cm2, p2f, b, sh_d, sh_i);
        } else {
            ull keys[16];
            load_striped<16>(keys, buf, bcnt);
            sort_rebased<16>(keys, bcnt, stemp.c, sh_u);
            role0_post<16>(keys, bcnt, cm2, p2f, b, sh_d, sh_i);
        }
    } else {
        // ---------------- head sort + sampling ----------------
        const int hcnt = min(g_hcnt[b], HDCAP);
        const float invf = g_invf[b];
        const float p1 = topps[b];
        const float thr = invf * minps[b];   // ps[0] * min_p  (top e == 1.0)
        const ull* buf = &g_head[(size_t)b * HDCAP];

        if (hcnt <= 2560) {
            ull keys[10];
            load_striped<10>(keys, buf, hcnt);
            sort_rebased<10>(keys, hcnt, stemp.b, sh_u);
            role1_post<10>(keys, hcnt, invf, p1, thr, topks, uu, out, b, sh_d, sh_i);
        } else {
            ull keys[16];
            load_striped<16>(keys, buf, hcnt);
            sort_rebased<16>(keys, hcnt, stemp.c, sh_u);
            role1_post<16>(keys, hcnt, invf, p1, thr, topks, uu, out, b, sh_d, sh_i);
        }
    }
}

// ---------------------------------------------------------------------------
// K3: coalesced logprob matrix, 5 float4 per thread (MLP=5); membership iff
// key <= Kstar.  Writes next_token_logprobs once.  grid (25, SB) x 256.
// ---------------------------------------------------------------------------
__global__ __launch_bounds__(256) void k3_kernel(float* __restrict__ out) {
    const int b = blockIdx.y;
    const int t = threadIdx.x;
    const float invf = g_invf[b];
    const float S2f = g_S2f[b];
    const ull Kst = g_kstar[b];
    const unsigned khi = (unsigned)(Kst >> 17);
    const unsigned klo = (unsigned)(Kst & 0x1FFFFull);

    const float4* ework = (const float4*)(g_work + (size_t)b * SV);
    float4* orow = (float4*)(out + (size_t)SB + (size_t)b * SV);

    float4 e[5];
    int qs[5];
#pragma unroll
    for (int i = 0; i < 5; i++) {
        qs[i] = blockIdx.x * 1280 + i * 256 + t;
        e[i] = ework[qs[i]];
    }
#pragma unroll
    for (int i = 0; i < 5; i++) {
        float ev[4] = {e[i].x, e[i].y, e[i].z, e[i].w};
        float ov[4];
#pragma unroll
        for (int c = 0; c < 4; c++) {
            float p = ev[c] * invf;
            unsigned pk = 0x7FFFFFFFu - __float_as_uint(p);
            bool mem = (pk < khi) || (pk == khi && (unsigned)(qs[i] * 4 + c) <= klo);
            ov[c] = mem ? fmaxf(logf(p / S2f), -FLT_MAX) : -FLT_MAX;
        }
        orow[qs[i]] = make_float4(ov[0], ov[1], ov[2], ov[3]);
    }

    if (blockIdx.x == 0 && t == 0) {
        ull kk = g_sampkey[b];
        float psf = key_p(kk);
        float nlp = (kk <= Kst) ? fmaxf(logf(psf / S2f), -FLT_MAX) : -FLT_MAX;
        out[(size_t)SB + (size_t)SB * SV + b] = nlp;
    }
}

// ---------------------------------------------------------------------------
// Host launcher (graph-capturable: kernel launches only)
// ---------------------------------------------------------------------------
extern "C" void kernel_launch(void* const* d_in, const int* in_sizes, int n_in,
                              void* d_out, int out_size) {
    const float* logits = (const float*)d_in[0];
    const float* temps  = (const float*)d_in[1];
    const int*   topks  = (const int*)d_in[2];
    const float* topps  = (const float*)d_in[3];
    const float* topps2 = (const float*)d_in[4];
    const float* minps  = (const float*)d_in[5];
    const float* u      = (const float*)d_in[6];
    float* out = (float*)d_out;

    const int sortBytes = (int)sizeof(SortTemp);
    cudaFuncSetAttribute(k2_kernel, cudaFuncAttributeMaxDynamicSharedMemorySize, sortBytes);

    dim3 g8(8, SB);
    k_max<<<g8, 512>>>(logits);
    k_exp<<<g8, 512>>>(logits, temps);
    k_gather<<<g8, 512>>>(topps2);
    k2_kernel<<<256, K2T, sortBytes>>>(topps2, topks, topps, minps, u, out);
    {
        dim3 g(25, SB);
        k3_kernel<<<g, 256>>>(out);
    }
}